// round 14
// baseline (speedup 1.0000x reference)
#include <cuda_runtime.h>
#include <stdint.h>

#define N_NODES 50000
#define IN_CH   256
#define ZD      64
#define NE      800000
#define SCAN_BLOCKS 49   // ceil(50000/1024)

// Scratch (no allocations allowed)
__device__ float g_xwmu[N_NODES * 64];  // x @ W_mu
__device__ float g_xwls[N_NODES * 64];  // x @ W_logstd
__device__ int   g_deg[N_NODES];
__device__ float g_dinv[N_NODES];
__device__ int   g_off[N_NODES + 1];    // CSR offsets (by dst)
__device__ int   g_cur[N_NODES];        // fill cursors
__device__ int   g_srcs[NE];            // CSR src indices grouped by dst
__device__ int   g_part[SCAN_BLOCKS];
__device__ int   g_poff[SCAN_BLOCKS];

// ---------------- degree ----------------
__global__ void k_deg_init() {
    int i = blockIdx.x * 256 + threadIdx.x;
    if (i < N_NODES) g_deg[i] = 1;   // self loop
}

// edge_index is int32
__global__ void k_deg_count(const int* __restrict__ ei) {
    int e = blockIdx.x * 256 + threadIdx.x;
    if (e < NE) atomicAdd(&g_deg[ei[NE + e]], 1);
}

// ---------------- scan phase 1 ----------------
__global__ void __launch_bounds__(1024) k_scan_partial() {
    __shared__ int wsum[32];
    int i = blockIdx.x * 1024 + threadIdx.x;
    int v = (i < N_NODES) ? (g_deg[i] - 1) : 0;
    const int lane = threadIdx.x & 31, wid = threadIdx.x >> 5;
    #pragma unroll
    for (int d = 16; d > 0; d >>= 1) v += __shfl_down_sync(0xffffffff, v, d);
    if (lane == 0) wsum[wid] = v;
    __syncthreads();
    if (wid == 0) {
        int s = wsum[lane];
        #pragma unroll
        for (int d = 16; d > 0; d >>= 1) s += __shfl_down_sync(0xffffffff, s, d);
        if (lane == 0) g_part[blockIdx.x] = s;
    }
}

// ---------------- scan phase 2 ----------------
__global__ void __launch_bounds__(64) k_scan_part() {
    __shared__ int w0;
    int t = threadIdx.x;
    const int lane = t & 31, wid = t >> 5;
    int v = (t < SCAN_BLOCKS) ? g_part[t] : 0;
    int incl = v;
    #pragma unroll
    for (int d = 1; d < 32; d <<= 1) {
        int u = __shfl_up_sync(0xffffffff, incl, d);
        if (lane >= d) incl += u;
    }
    if (wid == 0 && lane == 31) w0 = incl;
    __syncthreads();
    if (wid == 1) incl += w0;
    if (t < SCAN_BLOCKS) g_poff[t] = incl - v;
}

// ---------------- scan phase 3; fused dinv ----------------
__global__ void __launch_bounds__(1024) k_scan_final() {
    __shared__ int wsum[32];
    int i = blockIdx.x * 1024 + threadIdx.x;
    const int lane = threadIdx.x & 31, wid = threadIdx.x >> 5;
    int deg = (i < N_NODES) ? g_deg[i] : 1;
    int v = deg - 1;
    int incl = v;
    #pragma unroll
    for (int d = 1; d < 32; d <<= 1) {
        int u = __shfl_up_sync(0xffffffff, incl, d);
        if (lane >= d) incl += u;
    }
    if (lane == 31) wsum[wid] = incl;
    __syncthreads();
    if (wid == 0) {
        int ws = wsum[lane];
        int wincl = ws;
        #pragma unroll
        for (int d = 1; d < 32; d <<= 1) {
            int u = __shfl_up_sync(0xffffffff, wincl, d);
            if (lane >= d) wincl += u;
        }
        wsum[lane] = wincl - ws;
    }
    __syncthreads();
    int excl = g_poff[blockIdx.x] + wsum[wid] + incl - v;
    if (i < N_NODES) {
        g_off[i] = excl;
        g_cur[i] = excl;
        g_dinv[i] = rsqrtf((float)deg);
        if (i == N_NODES - 1) g_off[N_NODES] = excl + v;
    }
}

// ---------------- CSR fill ----------------
__global__ void k_fill(const int* __restrict__ ei) {
    int e = blockIdx.x * 256 + threadIdx.x;
    if (e >= NE) return;
    int dst = ei[NE + e];
    int pos = atomicAdd(&g_cur[dst], 1);
    g_srcs[pos] = ei[e];
}

// ---------------- per-head GEMM: 128 thr, 128x64 tile, K chunked 4x64 ----------------
// smem: ws[64][64] (16KB) + xs[64][128] (32KB) = 48KB -> 4 blocks/SM
__global__ void __launch_bounds__(128, 4) k_gemm_h(const float* __restrict__ x,
                                                   const float* __restrict__ W,
                                                   float* __restrict__ g) {
    extern __shared__ float smem[];
    float* ws = smem;              // [64][64]  ws[k][c]
    float* xs = smem + 64 * 64;    // [64][128] xs[k][r]
    const int tid = threadIdx.x;
    const int rowBase = blockIdx.x * 128;

    const int rg = tid >> 3;   // 0..15
    const int cg = tid & 7;    // 0..7
    const int r0 = rg * 8, c0 = cg * 8;

    unsigned long long acc[8][4];
    #pragma unroll
    for (int r = 0; r < 8; r++)
        #pragma unroll
        for (int c = 0; c < 4; c++) acc[r][c] = 0ull;

    const float4* W4 = (const float4*)W;
    const float4* x4 = (const float4*)x;
    const int grow_me = rowBase + tid;

    #pragma unroll
    for (int ch = 0; ch < 4; ch++) {
        // W chunk: 64 k-rows x 64 cols = 1024 float4
        {
            float4* ws4 = (float4*)ws;
            #pragma unroll
            for (int f = tid; f < 64 * 16; f += 128) {
                int k = f >> 4, c4 = f & 15;
                ws4[f] = W4[(ch * 64 + k) * 16 + c4];
            }
        }
        // x chunk transposed: each thread owns one row
        {
            #pragma unroll 4
            for (int k4 = 0; k4 < 16; k4++) {
                int kl = k4 * 4;
                float4 v = make_float4(0.f, 0.f, 0.f, 0.f);
                if (grow_me < N_NODES) v = x4[(size_t)grow_me * 64 + ((ch * 64 + kl) >> 2)];
                xs[(kl + 0) * 128 + tid] = v.x;
                xs[(kl + 1) * 128 + tid] = v.y;
                xs[(kl + 2) * 128 + tid] = v.z;
                xs[(kl + 3) * 128 + tid] = v.w;
            }
        }
        __syncthreads();

        #pragma unroll 4
        for (int k = 0; k < 64; k++) {
            float4 xa = *(const float4*)&xs[k * 128 + r0];
            float4 xb = *(const float4*)&xs[k * 128 + r0 + 4];
            ulonglong2 wa = *(const ulonglong2*)&ws[k * 64 + c0];
            ulonglong2 wb = *(const ulonglong2*)&ws[k * 64 + c0 + 4];
            float xv[8] = {xa.x, xa.y, xa.z, xa.w, xb.x, xb.y, xb.z, xb.w};
            unsigned long long wv[4] = {wa.x, wa.y, wb.x, wb.y};
            #pragma unroll
            for (int r = 0; r < 8; r++) {
                unsigned int xu = __float_as_uint(xv[r]);
                unsigned long long x2;
                asm("mov.b64 %0, {%1, %1};" : "=l"(x2) : "r"(xu));
                #pragma unroll
                for (int c = 0; c < 4; c++) {
                    asm("fma.rn.f32x2 %0, %1, %2, %0;"
                        : "+l"(acc[r][c]) : "l"(x2), "l"(wv[c]));
                }
            }
        }
        __syncthreads();
    }

    #pragma unroll
    for (int r = 0; r < 8; r++) {
        int grow = rowBase + r0 + r;
        if (grow >= N_NODES) break;
        #pragma unroll
        for (int c = 0; c < 4; c++) {
            unsigned int lo, hi;
            asm("mov.b64 {%0, %1}, %2;" : "=r"(lo), "=r"(hi) : "l"(acc[r][c]));
            float2 v = make_float2(__uint_as_float(lo), __uint_as_float(hi));
            *(float2*)&g[(size_t)grow * 64 + c0 + c * 2] = v;
        }
    }
}

// ---------------- per-head gather: warp per node, float2 per lane ----------------
__global__ void __launch_bounds__(256) k_gather_h(const float* __restrict__ xwh,
                                                  const float* __restrict__ bias,
                                                  float* __restrict__ outh) {
    int n    = blockIdx.x * 8 + (threadIdx.x >> 5);
    int lane = threadIdx.x & 31;
    if (n >= N_NODES) return;
    float dn = g_dinv[n];
    const float2* xw2 = (const float2*)xwh;

    float2 self = xw2[(size_t)n * 32 + lane];
    float w = dn * dn;
    float2 acc = make_float2(self.x * w, self.y * w);

    int e0 = g_off[n], e1 = g_off[n + 1];
    int e = e0;
    for (; e + 4 <= e1; e += 4) {
        int s0 = g_srcs[e], s1 = g_srcs[e + 1], s2 = g_srcs[e + 2], s3 = g_srcs[e + 3];
        float n0 = g_dinv[s0] * dn, n1 = g_dinv[s1] * dn;
        float n2 = g_dinv[s2] * dn, n3 = g_dinv[s3] * dn;
        float2 v0 = xw2[(size_t)s0 * 32 + lane];
        float2 v1 = xw2[(size_t)s1 * 32 + lane];
        float2 v2 = xw2[(size_t)s2 * 32 + lane];
        float2 v3 = xw2[(size_t)s3 * 32 + lane];
        acc.x += v0.x * n0; acc.y += v0.y * n0;
        acc.x += v1.x * n1; acc.y += v1.y * n1;
        acc.x += v2.x * n2; acc.y += v2.y * n2;
        acc.x += v3.x * n3; acc.y += v3.y * n3;
    }
    for (; e < e1; e++) {
        int s = g_srcs[e];
        float nrm = g_dinv[s] * dn;
        float2 v = xw2[(size_t)s * 32 + lane];
        acc.x += v.x * nrm; acc.y += v.y * nrm;
    }

    float2 b = ((const float2*)bias)[lane];
    acc.x += b.x; acc.y += b.y;

    ((float2*)outh)[(size_t)n * 32 + lane] = acc;
}

extern "C" void kernel_launch(void* const* d_in, const int* in_sizes, int n_in,
                              void* d_out, int out_size) {
    const float* x   = (const float*)d_in[0];
    const int*   ei  = (const int*)d_in[1];      // int32 edge_index [2][NE]
    const float* Wmu = (const float*)d_in[2];
    const float* bmu = (const float*)d_in[3];
    const float* Wls = (const float*)d_in[4];
    const float* bls = (const float*)d_in[5];
    float* out = (float*)d_out;

    (void)in_sizes; (void)n_in; (void)out_size;

    static cudaStream_t s_mu = nullptr, s_ls = nullptr;
    static cudaEvent_t  ev_fork = nullptr, ev_mu = nullptr, ev_ls = nullptr;
    if (s_mu == nullptr) {
        cudaStreamCreateWithFlags(&s_mu, cudaStreamNonBlocking);
        cudaStreamCreateWithFlags(&s_ls, cudaStreamNonBlocking);
        cudaEventCreateWithFlags(&ev_fork, cudaEventDisableTiming);
        cudaEventCreateWithFlags(&ev_mu, cudaEventDisableTiming);
        cudaEventCreateWithFlags(&ev_ls, cudaEventDisableTiming);
    }

    const int GB = (N_NODES + 127) / 128;   // 391 blocks per head

    // Fork: two independent head GEMMs on side streams
    cudaEventRecord(ev_fork, 0);
    cudaStreamWaitEvent(s_mu, ev_fork, 0);
    cudaStreamWaitEvent(s_ls, ev_fork, 0);
    k_gemm_h<<<GB, 128, 49152, s_mu>>>(x, Wmu, g_xwmu);
    cudaEventRecord(ev_mu, s_mu);
    k_gemm_h<<<GB, 128, 49152, s_ls>>>(x, Wls, g_xwls);
    cudaEventRecord(ev_ls, s_ls);

    // CSR-build branch on the main stream
    k_deg_init    <<<(N_NODES + 255) / 256, 256>>>();
    k_deg_count   <<<(NE + 255) / 256, 256>>>(ei);
    k_scan_partial<<<SCAN_BLOCKS, 1024>>>();
    k_scan_part   <<<1, 64>>>();
    k_scan_final  <<<SCAN_BLOCKS, 1024>>>();
    k_fill        <<<(NE + 255) / 256, 256>>>(ei);

    // mu gather as soon as mu GEMM + CSR are done (overlaps ls GEMM tail)
    cudaStreamWaitEvent(0, ev_mu, 0);
    k_gather_h<<<(N_NODES + 7) / 8, 256>>>(g_xwmu, bmu, out);

    cudaStreamWaitEvent(0, ev_ls, 0);
    k_gather_h<<<(N_NODES + 7) / 8, 256>>>(g_xwls, bls, out + (size_t)N_NODES * 64);
}

// round 17
// speedup vs baseline: 22.4749x; 22.4749x over previous
#include <cuda_runtime.h>
#include <stdint.h>

#define N_NODES 50000
#define IN_CH   256
#define ZD      64
#define NE      800000
#define SCAN_BLOCKS 49   // ceil(50000/1024)

// Scratch (no allocations allowed)
__device__ float g_xw[N_NODES * 128];   // fused xw = x @ [W_mu | W_logstd]
__device__ int   g_deg[N_NODES];
__device__ float g_dinv[N_NODES];
__device__ int   g_off[N_NODES + 1];    // CSR offsets (by dst)
__device__ int   g_cur[N_NODES];        // fill cursors
__device__ int   g_srcs[NE];            // CSR src indices grouped by dst
__device__ int   g_part[SCAN_BLOCKS];   // per-block partial sums
__device__ int   g_poff[SCAN_BLOCKS];   // per-block exclusive offsets

// ---------------- degree ----------------
__global__ void k_deg_init() {
    int i = blockIdx.x * 256 + threadIdx.x;
    if (i < N_NODES) g_deg[i] = 1;   // self loop
}

// edge_index is int32
__global__ void k_deg_count(const int* __restrict__ ei) {
    int e = blockIdx.x * 256 + threadIdx.x;
    if (e < NE) atomicAdd(&g_deg[ei[NE + e]], 1);
}

// ---------------- scan phase 1: per-block reduction of (deg-1) ----------------
__global__ void __launch_bounds__(1024) k_scan_partial() {
    __shared__ int wsum[32];
    int i = blockIdx.x * 1024 + threadIdx.x;
    int v = (i < N_NODES) ? (g_deg[i] - 1) : 0;
    const int lane = threadIdx.x & 31, wid = threadIdx.x >> 5;
    #pragma unroll
    for (int d = 16; d > 0; d >>= 1) v += __shfl_down_sync(0xffffffff, v, d);
    if (lane == 0) wsum[wid] = v;
    __syncthreads();
    if (wid == 0) {
        int s = wsum[lane];
        #pragma unroll
        for (int d = 16; d > 0; d >>= 1) s += __shfl_down_sync(0xffffffff, s, d);
        if (lane == 0) g_part[blockIdx.x] = s;
    }
}

// ---------------- scan phase 2: exclusive scan of 49 partials ----------------
__global__ void __launch_bounds__(64) k_scan_part() {
    __shared__ int w0;
    int t = threadIdx.x;
    const int lane = t & 31, wid = t >> 5;
    int v = (t < SCAN_BLOCKS) ? g_part[t] : 0;
    int incl = v;
    #pragma unroll
    for (int d = 1; d < 32; d <<= 1) {
        int u = __shfl_up_sync(0xffffffff, incl, d);
        if (lane >= d) incl += u;
    }
    if (wid == 0 && lane == 31) w0 = incl;
    __syncthreads();
    if (wid == 1) incl += w0;
    if (t < SCAN_BLOCKS) g_poff[t] = incl - v;
}

// ---------------- scan phase 3: block-local scan + offsets; fused dinv ----------------
__global__ void __launch_bounds__(1024) k_scan_final() {
    __shared__ int wsum[32];
    int i = blockIdx.x * 1024 + threadIdx.x;
    const int lane = threadIdx.x & 31, wid = threadIdx.x >> 5;
    int deg = (i < N_NODES) ? g_deg[i] : 1;
    int v = deg - 1;
    int incl = v;
    #pragma unroll
    for (int d = 1; d < 32; d <<= 1) {
        int u = __shfl_up_sync(0xffffffff, incl, d);
        if (lane >= d) incl += u;
    }
    if (lane == 31) wsum[wid] = incl;
    __syncthreads();
    if (wid == 0) {
        int ws = wsum[lane];
        int wincl = ws;
        #pragma unroll
        for (int d = 1; d < 32; d <<= 1) {
            int u = __shfl_up_sync(0xffffffff, wincl, d);
            if (lane >= d) wincl += u;
        }
        wsum[lane] = wincl - ws;
    }
    __syncthreads();
    int excl = g_poff[blockIdx.x] + wsum[wid] + incl - v;
    if (i < N_NODES) {
        g_off[i] = excl;
        g_cur[i] = excl;
        g_dinv[i] = rsqrtf((float)deg);
        if (i == N_NODES - 1) g_off[N_NODES] = excl + v;
    }
}

// ---------------- CSR fill (int atomics only) ----------------
__global__ void k_fill(const int* __restrict__ ei) {
    int e = blockIdx.x * 256 + threadIdx.x;
    if (e >= NE) return;
    int dst = ei[NE + e];
    int pos = atomicAdd(&g_cur[dst], 1);
    g_srcs[pos] = ei[e];
}

// ---------------- GEMM: 128 thr, 64x128 tile, K chunked 4x64, f32x2 FFMA ----------------
// smem: ws[64][128] (32KB) + xs[64][64] (16KB) = 48KB -> 4 blocks/SM, 4 warps/SMSP
__global__ void __launch_bounds__(128, 4) k_gemm(const float* __restrict__ x,
                                                 const float* __restrict__ Wmu,
                                                 const float* __restrict__ Wls) {
    extern __shared__ float smem[];
    float* ws = smem;              // [64][128]
    float* xs = smem + 64 * 128;   // [64][64]
    const int tid = threadIdx.x;
    const int rowBase = blockIdx.x * 64;

    const int rg = tid >> 4;   // 0..7
    const int cg = tid & 15;   // 0..15
    const int r0 = rg * 8, c0 = cg * 8;

    unsigned long long acc[8][4];
    #pragma unroll
    for (int r = 0; r < 8; r++)
        #pragma unroll
        for (int c = 0; c < 4; c++) acc[r][c] = 0ull;

    const float4* Wmu4 = (const float4*)Wmu;
    const float4* Wls4 = (const float4*)Wls;
    const float4* x4   = (const float4*)x;

    #pragma unroll
    for (int ch = 0; ch < 4; ch++) {
        // W chunk: k rows [ch*64, ch*64+64), fused 128 cols
        {
            float4* ws4 = (float4*)ws;
            #pragma unroll
            for (int f = tid; f < 64 * 32; f += 128) {
                int k = f >> 5, c4 = f & 31;
                int kk = ch * 64 + k;
                ws4[f] = (c4 < 16) ? Wmu4[kk * 16 + c4] : Wls4[kk * 16 + (c4 - 16)];
            }
        }
        // x chunk transposed: xs[k_local][r], k_local in [0,64)
        {
            int r  = tid & 63;
            int kh = tid >> 6;          // 0/1 -> k-halves of 32
            int grow = rowBase + r;
            #pragma unroll
            for (int k4 = 0; k4 < 8; k4++) {
                int kl = kh * 32 + k4 * 4;
                float4 v = make_float4(0.f, 0.f, 0.f, 0.f);
                if (grow < N_NODES) v = x4[(size_t)grow * 64 + ((ch * 64 + kl) >> 2)];
                xs[(kl + 0) * 64 + r] = v.x;
                xs[(kl + 1) * 64 + r] = v.y;
                xs[(kl + 2) * 64 + r] = v.z;
                xs[(kl + 3) * 64 + r] = v.w;
            }
        }
        __syncthreads();

        #pragma unroll 4
        for (int k = 0; k < 64; k++) {
            float4 xa = *(const float4*)&xs[k * 64 + r0];
            float4 xb = *(const float4*)&xs[k * 64 + r0 + 4];
            ulonglong2 wa = *(const ulonglong2*)&ws[k * 128 + c0];
            ulonglong2 wb = *(const ulonglong2*)&ws[k * 128 + c0 + 4];
            float xv[8] = {xa.x, xa.y, xa.z, xa.w, xb.x, xb.y, xb.z, xb.w};
            unsigned long long wv[4] = {wa.x, wa.y, wb.x, wb.y};
            #pragma unroll
            for (int r = 0; r < 8; r++) {
                unsigned int xu = __float_as_uint(xv[r]);
                unsigned long long x2;
                asm("mov.b64 %0, {%1, %1};" : "=l"(x2) : "r"(xu));
                #pragma unroll
                for (int c = 0; c < 4; c++) {
                    asm("fma.rn.f32x2 %0, %1, %2, %0;"
                        : "+l"(acc[r][c]) : "l"(x2), "l"(wv[c]));
                }
            }
        }
        __syncthreads();
    }

    #pragma unroll
    for (int r = 0; r < 8; r++) {
        int grow = rowBase + r0 + r;
        if (grow >= N_NODES) break;
        #pragma unroll
        for (int c = 0; c < 4; c++) {
            unsigned int lo, hi;
            asm("mov.b64 {%0, %1}, %2;" : "=r"(lo), "=r"(hi) : "l"(acc[r][c]));
            float2 v = make_float2(__uint_as_float(lo), __uint_as_float(hi));
            *(float2*)&g_xw[(size_t)grow * 128 + c0 + c * 2] = v;
        }
    }
}

// ---------------- gather: warp per node, unroll 8 for MLP ----------------
__global__ void __launch_bounds__(256) k_gather(const float* __restrict__ bmu,
                                                const float* __restrict__ bls,
                                                float* __restrict__ out) {
    int n    = blockIdx.x * 8 + (threadIdx.x >> 5);
    int lane = threadIdx.x & 31;
    if (n >= N_NODES) return;
    float dn = g_dinv[n];
    const float4* xw4 = (const float4*)g_xw;

    float4 self = xw4[(size_t)n * 32 + lane];
    float w = dn * dn;
    float4 acc = make_float4(self.x * w, self.y * w, self.z * w, self.w * w);

    int e0 = g_off[n], e1 = g_off[n + 1];
    int e = e0;
    for (; e + 8 <= e1; e += 8) {
        int s[8];
        #pragma unroll
        for (int j = 0; j < 8; j++) s[j] = g_srcs[e + j];
        float nr[8];
        #pragma unroll
        for (int j = 0; j < 8; j++) nr[j] = g_dinv[s[j]] * dn;
        float4 v[8];
        #pragma unroll
        for (int j = 0; j < 8; j++) v[j] = xw4[(size_t)s[j] * 32 + lane];
        #pragma unroll
        for (int j = 0; j < 8; j++) {
            acc.x += v[j].x * nr[j]; acc.y += v[j].y * nr[j];
            acc.z += v[j].z * nr[j]; acc.w += v[j].w * nr[j];
        }
    }
    for (; e < e1; e++) {
        int s = g_srcs[e];
        float nrm = g_dinv[s] * dn;
        float4 v = xw4[(size_t)s * 32 + lane];
        acc.x += v.x * nrm; acc.y += v.y * nrm;
        acc.z += v.z * nrm; acc.w += v.w * nrm;
    }

    const float4* b4 = (lane < 16) ? (const float4*)bmu : (const float4*)bls;
    float4 b = b4[lane & 15];
    acc.x += b.x; acc.y += b.y; acc.z += b.z; acc.w += b.w;

    size_t oidx = (lane < 16) ? ((size_t)n * 16 + lane)
                              : ((size_t)N_NODES * 16 + (size_t)n * 16 + (lane - 16));
    ((float4*)out)[oidx] = acc;
}

extern "C" void kernel_launch(void* const* d_in, const int* in_sizes, int n_in,
                              void* d_out, int out_size) {
    const float* x   = (const float*)d_in[0];
    const int*   ei  = (const int*)d_in[1];      // int32 edge_index [2][NE]
    const float* Wmu = (const float*)d_in[2];
    const float* bmu = (const float*)d_in[3];
    const float* Wls = (const float*)d_in[4];
    const float* bls = (const float*)d_in[5];
    float* out = (float*)d_out;

    (void)in_sizes; (void)n_in; (void)out_size;

    static cudaStream_t s_gemm = nullptr;
    static cudaEvent_t  ev_fork = nullptr, ev_join = nullptr;
    if (s_gemm == nullptr) {
        cudaStreamCreateWithFlags(&s_gemm, cudaStreamNonBlocking);
        cudaEventCreateWithFlags(&ev_fork, cudaEventDisableTiming);
        cudaEventCreateWithFlags(&ev_join, cudaEventDisableTiming);
    }

    // Fork: GEMM branch (independent of edge processing)
    cudaEventRecord(ev_fork, 0);
    cudaStreamWaitEvent(s_gemm, ev_fork, 0);
    k_gemm<<<(N_NODES + 63) / 64, 128, 49152, s_gemm>>>(x, Wmu, Wls);
    cudaEventRecord(ev_join, s_gemm);

    // CSR-build branch on the main stream
    k_deg_init    <<<(N_NODES + 255) / 256, 256>>>();
    k_deg_count   <<<(NE + 255) / 256, 256>>>(ei);
    k_scan_partial<<<SCAN_BLOCKS, 1024>>>();
    k_scan_part   <<<1, 64>>>();
    k_scan_final  <<<SCAN_BLOCKS, 1024>>>();
    k_fill        <<<(NE + 255) / 256, 256>>>(ei);

    // Join, then gather (needs g_xw + CSR)
    cudaStreamWaitEvent(0, ev_join, 0);
    k_gather<<<(N_NODES + 7) / 8, 256>>>(bmu, bls, out);
}